// round 9
// baseline (speedup 1.0000x reference)
#include <cuda_runtime.h>
#include <cuda_bf16.h>
#include <math.h>
#include <stdint.h>

// ---------------------------------------------------------------- constants
#define B_      4096
#define N_      8192              // 2B rows
#define C_      128               // feature dim
#define MT      128               // rows per CTA stripe
#define NT      128               // cols per j-tile
#define TT      32                // tiles per j-half (4096/128)
#define THREADS 256
#define PITCH   272               // smem row pitch (256B data + 16B pad)
#define LOG2E2  2.8853900817779268f   // (2/T==2? no: 1/T * log2 e) -> 2*log2(e)
#define LN2     0.6931471805599453f

// scratch (__device__ globals: allocation-free)
__device__ __nv_bfloat16 g_RA[N_ * C_];   // normalized reps * LOG2E2 (A side)
__device__ __nv_bfloat16 g_RB[N_ * C_];   // normalized reps (B side)
__device__ float g_rowsum[N_];            // sum_j exp(2*sim_ij), diag excluded
__device__ float g_pos[N_];               // LOG2E2 * sim(i, (i+B) mod N)

// ---------------------------------------------------------------- helpers
__device__ __forceinline__ uint32_t smem_u32(const void* p) {
    uint32_t a;
    asm("{ .reg .u64 t; cvta.to.shared.u64 t, %1; cvt.u32.u64 %0, t; }"
        : "=r"(a) : "l"(p));
    return a;
}

__device__ __forceinline__ void ldsm_x4(uint32_t (&r)[4], uint32_t addr) {
    asm volatile("ldmatrix.sync.aligned.m8n8.x4.shared.b16 {%0,%1,%2,%3}, [%4];"
                 : "=r"(r[0]), "=r"(r[1]), "=r"(r[2]), "=r"(r[3]) : "r"(addr));
}

__device__ __forceinline__ void mma16816(float (&d)[4], const uint32_t* a,
                                         uint32_t b0, uint32_t b1) {
    asm volatile(
        "mma.sync.aligned.m16n8k16.row.col.f32.bf16.bf16.f32 "
        "{%0,%1,%2,%3}, {%4,%5,%6,%7}, {%8,%9}, {%0,%1,%2,%3};"
        : "+f"(d[0]), "+f"(d[1]), "+f"(d[2]), "+f"(d[3])
        : "r"(a[0]), "r"(a[1]), "r"(a[2]), "r"(a[3]), "r"(b0), "r"(b1));
}

__device__ __forceinline__ float ex2(float x) {
    float r;
    asm("ex2.approx.f32 %0, %1;" : "=f"(r) : "f"(x));
    return r;
}

#define CP_ASYNC16(saddr, gptr) \
    asm volatile("cp.async.cg.shared.global [%0], [%1], 16;" \
                 :: "r"(saddr), "l"(gptr))
#define CP_COMMIT()  asm volatile("cp.async.commit_group;" ::: "memory")
#define CP_WAIT0()   asm volatile("cp.async.wait_group 0;" ::: "memory")

// ---------------------------------------------------------------- kernel 1
// L2-normalize rows of [z_i; z_j]; write bf16 unscaled (B side) and
// bf16 scaled by LOG2E2 (A side). Also zero g_rowsum.
__global__ void __launch_bounds__(256) normalize_kernel(
    const float* __restrict__ zi, const float* __restrict__ zj)
{
    const int w = threadIdx.x >> 5, lane = threadIdx.x & 31;
    const int row = blockIdx.x * 8 + w;
    const float* src = (row < B_) ? (zi + (size_t)row * C_)
                                  : (zj + (size_t)(row - B_) * C_);
    float4 v = ((const float4*)src)[lane];
    float ss = v.x * v.x + v.y * v.y + v.z * v.z + v.w * v.w;
    #pragma unroll
    for (int o = 16; o; o >>= 1) ss += __shfl_xor_sync(0xffffffffu, ss, o);
    const float rn  = rsqrtf(ss);
    const float rnA = rn * LOG2E2;

    __nv_bfloat162 b0 = __floats2bfloat162_rn(v.x * rn, v.y * rn);
    __nv_bfloat162 b1 = __floats2bfloat162_rn(v.z * rn, v.w * rn);
    uint2 pb = { *(uint32_t*)&b0, *(uint32_t*)&b1 };
    ((uint2*)(g_RB + (size_t)row * C_))[lane] = pb;

    __nv_bfloat162 a0 = __floats2bfloat162_rn(v.x * rnA, v.y * rnA);
    __nv_bfloat162 a1 = __floats2bfloat162_rn(v.z * rnA, v.w * rnA);
    uint2 pa = { *(uint32_t*)&a0, *(uint32_t*)&a1 };
    ((uint2*)(g_RA + (size_t)row * C_))[lane] = pa;

    if (blockIdx.x < 32) g_rowsum[blockIdx.x * 256 + threadIdx.x] = 0.f;
}

// ---------------------------------------------------------------- kernel 2
// Fused sim-GEMM (HMMA bf16) + exp-rowsum epilogue.
// A fragments persist in registers across all 32 j-tiles; B tiles are
// double-buffered in smem via cp.async. acc is pre-scaled by LOG2E2 through A.
extern "C" __global__ void __launch_bounds__(THREADS, 1) ntxent_mma_kernel()
{
    extern __shared__ char smraw[];
    const uint32_t sA32 = smem_u32(smraw);
    const uint32_t sB32 = sA32 + MT * PITCH;

    const int tid  = threadIdx.x;
    const int lane = tid & 31, w = tid >> 5;
    const int wm = w & 3, wn = w >> 2;
    const int ibase  = (blockIdx.x >> 1) * MT;
    const int jh     = blockIdx.x & 1;
    const int jhbase = jh * 4096;
    const int iw     = ibase + wm * 32;              // warp's 32-row window
    const int pw     = (iw + B_) & (N_ - 1);         // positive-col window

    // per-thread smem copy slots (16 chunks of 16B per 128x256B tile / 256 thr -> 8 each)
    const int cm = tid >> 4, cq = tid & 15;          // row 0..15(+16k), 16B col 0..15

    // prologue: A stripe (plain) + B tile 0 (cp.async)
    #pragma unroll
    for (int p = 0; p < 8; p++) {
        const int m = p * 16 + cm;
        *(float4*)(smraw + m * PITCH + cq * 16) =
            *(const float4*)(g_RA + (size_t)(ibase + m) * C_ + cq * 8);
        CP_ASYNC16(sB32 + (uint32_t)(m * PITCH + cq * 16),
                   g_RB + (size_t)(jhbase + m) * C_ + cq * 8);
    }
    CP_COMMIT();
    CP_WAIT0();
    __syncthreads();

    // persistent A fragments: [ks][mf][4]
    const int lrow = lane & 15;
    const int lkb  = (lane >> 4) * 16;
    const uint32_t aAddr = sA32 + (uint32_t)((wm * 32 + lrow) * PITCH + lkb);
    uint32_t aReg[8][2][4];
    #pragma unroll
    for (int ks = 0; ks < 8; ks++) {
        ldsm_x4(aReg[ks][0], aAddr + (uint32_t)(ks * 32));
        ldsm_x4(aReg[ks][1], aAddr + (uint32_t)(16 * PITCH + ks * 32));
    }

    const uint32_t bOffs = (uint32_t)((wn * 64 + lrow) * PITCH + lkb);
    float rs[4] = {0.f, 0.f, 0.f, 0.f};
    const int rquad = lane >> 2;
    const int cpair = (lane & 3) * 2;

    for (int t = 0; t < TT; t++) {
        const uint32_t bufR = sB32 + (uint32_t)((t & 1) * (MT * PITCH));

        // async prefetch of next B tile into the other buffer
        if (t + 1 < TT) {
            const uint32_t bufW = sB32 + (uint32_t)(((t + 1) & 1) * (MT * PITCH));
            const int gb = jhbase + (t + 1) * NT;
            #pragma unroll
            for (int p = 0; p < 8; p++) {
                const int m = p * 16 + cm;
                CP_ASYNC16(bufW + (uint32_t)(m * PITCH + cq * 16),
                           g_RB + (size_t)(gb + m) * C_ + cq * 8);
            }
            CP_COMMIT();
        }

        float acc[2][8][4];
        #pragma unroll
        for (int mf = 0; mf < 2; mf++)
            #pragma unroll
            for (int nf = 0; nf < 8; nf++)
                #pragma unroll
                for (int e = 0; e < 4; e++) acc[mf][nf][e] = 0.f;

        #pragma unroll
        for (int ks = 0; ks < 8; ks++) {
            uint32_t b[4][4];
            #pragma unroll
            for (int n16 = 0; n16 < 4; n16++)
                ldsm_x4(b[n16], bufR + bOffs + (uint32_t)(n16 * 16 * PITCH + ks * 32));
            #pragma unroll
            for (int mf = 0; mf < 2; mf++)
                #pragma unroll
                for (int nf = 0; nf < 8; nf++) {
                    const int n16 = nf >> 1, g = nf & 1;
                    mma16816(acc[mf][nf], aReg[ks][mf], b[n16][g], b[n16][g + 2]);
                }
        }

        // fused epilogue: acc is already LOG2E2*sim -> ex2 directly
        const int jt = jhbase + t * NT + wn * 64;
        #pragma unroll
        for (int nf = 0; nf < 8; nf++) {
            const int jb = jt + nf * 8;
            const bool hd = (unsigned)(jb - iw) < 32u;   // diag in this frag col
            const bool hp = (unsigned)(jb - pw) < 32u;   // pos  in this frag col
            if (!hd && !hp) {
                #pragma unroll
                for (int mf = 0; mf < 2; mf++)
                    #pragma unroll
                    for (int e = 0; e < 4; e++)
                        rs[mf * 2 + (e >> 1)] += ex2(acc[mf][nf][e]);
            } else {
                #pragma unroll
                for (int mf = 0; mf < 2; mf++)
                    #pragma unroll
                    for (int e = 0; e < 4; e++) {
                        const int ie = iw + mf * 16 + rquad + ((e & 2) ? 8 : 0);
                        const int je = jb + cpair + (e & 1);
                        const float d = acc[mf][nf][e];
                        if (je == ((ie + B_) & (N_ - 1))) g_pos[ie] = d;
                        rs[mf * 2 + (e >> 1)] += (je == ie) ? 0.f : ex2(d);
                    }
            }
        }

        if (t + 1 < TT) CP_WAIT0();
        __syncthreads();
    }

    // reduce rowsums across the lane quad
    #pragma unroll
    for (int r = 0; r < 4; r++) {
        rs[r] += __shfl_xor_sync(0xffffffffu, rs[r], 1);
        rs[r] += __shfl_xor_sync(0xffffffffu, rs[r], 2);
    }
    if ((lane & 3) == 0) {
        #pragma unroll
        for (int r = 0; r < 4; r++) {
            const int row = iw + rquad + (r & 1) * 8 + (r >> 1) * 16;
            atomicAdd(&g_rowsum[row], rs[r]);
        }
    }
}

// ---------------------------------------------------------------- kernel 3
// loss_i = log(rowsum_i + 2^ps_i) - ps_i*ln2, ps = LOG2E2*pos (=2*pos*log2e)
__global__ void __launch_bounds__(1024) finalize_kernel(float* __restrict__ out)
{
    const int tid = threadIdx.x;
    float s = 0.f;
    #pragma unroll
    for (int r = tid; r < N_; r += 1024) {
        const float ps = g_pos[r];
        s += logf(g_rowsum[r] + ex2(ps)) - ps * LN2;
    }
    #pragma unroll
    for (int o = 16; o; o >>= 1) s += __shfl_xor_sync(0xffffffffu, s, o);
    __shared__ float sw[32];
    if ((tid & 31) == 0) sw[tid >> 5] = s;
    __syncthreads();
    if (tid < 32) {
        float v = sw[tid];
        #pragma unroll
        for (int o = 16; o; o >>= 1) v += __shfl_xor_sync(0xffffffffu, v, o);
        if (tid == 0) out[0] = v * (1.0f / (float)N_);
    }
}

// ---------------------------------------------------------------- launcher
extern "C" void kernel_launch(void* const* d_in, const int* in_sizes, int n_in,
                              void* d_out, int out_size)
{
    const float* zi = (const float*)d_in[0];
    const float* zj = (const float*)d_in[1];
    float* out = (float*)d_out;

    const int smem_bytes = 3 * MT * PITCH;   // A + 2x B buffers = 104448
    cudaFuncSetAttribute(ntxent_mma_kernel,
                         cudaFuncAttributeMaxDynamicSharedMemorySize, smem_bytes);

    normalize_kernel<<<N_ / 8, 256>>>(zi, zj);
    ntxent_mma_kernel<<<128, THREADS, smem_bytes>>>();
    finalize_kernel<<<1, 1024>>>(out);
}

// round 10
// speedup vs baseline: 1.1649x; 1.1649x over previous
#include <cuda_runtime.h>
#include <cuda_bf16.h>
#include <math.h>
#include <stdint.h>

// ---------------------------------------------------------------- constants
#define B_      4096
#define N_      8192              // 2B rows
#define C_      128               // feature dim
#define MT      128               // rows per CTA stripe
#define NT      128               // cols per j-tile
#define TT      32                // tiles per j-half (4096/128)
#define THREADS 512
#define PITCH   272               // smem row pitch (256B data + 16B pad)
#define LOG2E2  2.8853900817779268f   // 2*log2(e)  (= (1/T)*log2 e, T=0.5)
#define LN2     0.6931471805599453f

// scratch (__device__ globals: allocation-free)
__device__ __nv_bfloat16 g_RA[N_ * C_];   // normalized reps * LOG2E2 (A side)
__device__ __nv_bfloat16 g_RB[N_ * C_];   // normalized reps (B side)
__device__ float g_rowsum[N_];            // sum_j exp(2*sim_ij), diag excluded
__device__ float g_pos[N_];               // LOG2E2 * sim(i, (i+B) mod N)

// ---------------------------------------------------------------- helpers
__device__ __forceinline__ uint32_t smem_u32(const void* p) {
    uint32_t a;
    asm("{ .reg .u64 t; cvta.to.shared.u64 t, %1; cvt.u32.u64 %0, t; }"
        : "=r"(a) : "l"(p));
    return a;
}

__device__ __forceinline__ void ldsm_x4(uint32_t (&r)[4], uint32_t addr) {
    asm volatile("ldmatrix.sync.aligned.m8n8.x4.shared.b16 {%0,%1,%2,%3}, [%4];"
                 : "=r"(r[0]), "=r"(r[1]), "=r"(r[2]), "=r"(r[3]) : "r"(addr));
}

__device__ __forceinline__ void mma16816(float (&d)[4], const uint32_t* a,
                                         uint32_t b0, uint32_t b1) {
    asm volatile(
        "mma.sync.aligned.m16n8k16.row.col.f32.bf16.bf16.f32 "
        "{%0,%1,%2,%3}, {%4,%5,%6,%7}, {%8,%9}, {%0,%1,%2,%3};"
        : "+f"(d[0]), "+f"(d[1]), "+f"(d[2]), "+f"(d[3])
        : "r"(a[0]), "r"(a[1]), "r"(a[2]), "r"(a[3]), "r"(b0), "r"(b1));
}

__device__ __forceinline__ float ex2(float x) {
    float r;
    asm("ex2.approx.f32 %0, %1;" : "=f"(r) : "f"(x));
    return r;
}

#define CP_ASYNC16(saddr, gptr) \
    asm volatile("cp.async.cg.shared.global [%0], [%1], 16;" \
                 :: "r"(saddr), "l"(gptr))
#define CP_COMMIT()  asm volatile("cp.async.commit_group;" ::: "memory")
#define CP_WAIT0()   asm volatile("cp.async.wait_group 0;" ::: "memory")

// ---------------------------------------------------------------- kernel 1
__global__ void __launch_bounds__(256) normalize_kernel(
    const float* __restrict__ zi, const float* __restrict__ zj)
{
    const int w = threadIdx.x >> 5, lane = threadIdx.x & 31;
    const int row = blockIdx.x * 8 + w;
    const float* src = (row < B_) ? (zi + (size_t)row * C_)
                                  : (zj + (size_t)(row - B_) * C_);
    float4 v = ((const float4*)src)[lane];
    float ss = v.x * v.x + v.y * v.y + v.z * v.z + v.w * v.w;
    #pragma unroll
    for (int o = 16; o; o >>= 1) ss += __shfl_xor_sync(0xffffffffu, ss, o);
    const float rn  = rsqrtf(ss);
    const float rnA = rn * LOG2E2;

    __nv_bfloat162 b0 = __floats2bfloat162_rn(v.x * rn, v.y * rn);
    __nv_bfloat162 b1 = __floats2bfloat162_rn(v.z * rn, v.w * rn);
    uint2 pb = { *(uint32_t*)&b0, *(uint32_t*)&b1 };
    ((uint2*)(g_RB + (size_t)row * C_))[lane] = pb;

    __nv_bfloat162 a0 = __floats2bfloat162_rn(v.x * rnA, v.y * rnA);
    __nv_bfloat162 a1 = __floats2bfloat162_rn(v.z * rnA, v.w * rnA);
    uint2 pa = { *(uint32_t*)&a0, *(uint32_t*)&a1 };
    ((uint2*)(g_RA + (size_t)row * C_))[lane] = pa;

    if (blockIdx.x < 32) g_rowsum[blockIdx.x * 256 + threadIdx.x] = 0.f;
}

// ---------------------------------------------------------------- kernel 2
// Fused sim-GEMM (HMMA bf16) + exp-rowsum epilogue.
// 16 warps, 4(m) x 4(n), warp tile 32x32 -> 4 warps/SMSP for latency hiding.
// A fragments persist in registers; B double-buffered via cp.async.
extern "C" __global__ void __launch_bounds__(THREADS, 1) ntxent_mma_kernel()
{
    extern __shared__ char smraw[];
    const uint32_t sA32 = smem_u32(smraw);
    const uint32_t sB32 = sA32 + MT * PITCH;

    const int tid  = threadIdx.x;
    const int lane = tid & 31, w = tid >> 5;
    const int wm = w & 3, wn = w >> 2;               // 4 x 4 warp grid
    const int ibase  = (blockIdx.x >> 1) * MT;
    const int jh     = blockIdx.x & 1;
    const int jhbase = jh * 4096;
    const int iw     = ibase + wm * 32;              // warp's 32-row window
    const int pw     = (iw + B_) & (N_ - 1);         // positive-col window

    // per-thread copy slots: 512 thr x 16B = 8KB/pass; 32KB tile -> 4 passes
    const int cm = tid >> 4, cq = tid & 15;          // rows 0..31 (+32p), 16B col

    // prologue: A stripe (plain stores) + B tile 0 (cp.async)
    #pragma unroll
    for (int p = 0; p < 4; p++) {
        const int m = p * 32 + cm;
        *(float4*)(smraw + m * PITCH + cq * 16) =
            *(const float4*)(g_RA + (size_t)(ibase + m) * C_ + cq * 8);
        CP_ASYNC16(sB32 + (uint32_t)(m * PITCH + cq * 16),
                   g_RB + (size_t)(jhbase + m) * C_ + cq * 8);
    }
    CP_COMMIT();
    CP_WAIT0();
    __syncthreads();

    // persistent A fragments: [ks][mf][4]  (64 regs)
    const int lrow = lane & 15;
    const int lkb  = (lane >> 4) * 16;
    const uint32_t aAddr = sA32 + (uint32_t)((wm * 32 + lrow) * PITCH + lkb);
    uint32_t aReg[8][2][4];
    #pragma unroll
    for (int ks = 0; ks < 8; ks++) {
        ldsm_x4(aReg[ks][0], aAddr + (uint32_t)(ks * 32));
        ldsm_x4(aReg[ks][1], aAddr + (uint32_t)(16 * PITCH + ks * 32));
    }

    const uint32_t bOffs = (uint32_t)((wn * 32 + lrow) * PITCH + lkb);
    float rs[4] = {0.f, 0.f, 0.f, 0.f};
    const int rquad = lane >> 2;
    const int cpair = (lane & 3) * 2;

    for (int t = 0; t < TT; t++) {
        const uint32_t bufR = sB32 + (uint32_t)((t & 1) * (MT * PITCH));

        // async prefetch of next B tile into the other buffer
        if (t + 1 < TT) {
            const uint32_t bufW = sB32 + (uint32_t)(((t + 1) & 1) * (MT * PITCH));
            const int gb = jhbase + (t + 1) * NT;
            #pragma unroll
            for (int p = 0; p < 4; p++) {
                const int m = p * 32 + cm;
                CP_ASYNC16(bufW + (uint32_t)(m * PITCH + cq * 16),
                           g_RB + (size_t)(gb + m) * C_ + cq * 8);
            }
            CP_COMMIT();
        }

        float acc[2][4][4];
        #pragma unroll
        for (int mf = 0; mf < 2; mf++)
            #pragma unroll
            for (int nf = 0; nf < 4; nf++)
                #pragma unroll
                for (int e = 0; e < 4; e++) acc[mf][nf][e] = 0.f;

        #pragma unroll
        for (int ks = 0; ks < 8; ks++) {
            uint32_t b[2][4];
            ldsm_x4(b[0], bufR + bOffs + (uint32_t)(ks * 32));
            ldsm_x4(b[1], bufR + bOffs + (uint32_t)(16 * PITCH + ks * 32));
            #pragma unroll
            for (int mf = 0; mf < 2; mf++)
                #pragma unroll
                for (int nf = 0; nf < 4; nf++) {
                    const int n16 = nf >> 1, g = nf & 1;
                    mma16816(acc[mf][nf], aReg[ks][mf], b[n16][g], b[n16][g + 2]);
                }
        }

        // fused epilogue: acc is already LOG2E2*sim -> ex2 directly
        const int jt = jhbase + t * NT + wn * 32;
        #pragma unroll
        for (int nf = 0; nf < 4; nf++) {
            const int jb = jt + nf * 8;
            const bool hd = (unsigned)(jb - iw) < 32u;   // diag hits this frag
            const bool hp = (unsigned)(jb - pw) < 32u;   // pos  hits this frag
            if (!hd && !hp) {
                #pragma unroll
                for (int mf = 0; mf < 2; mf++)
                    #pragma unroll
                    for (int e = 0; e < 4; e++)
                        rs[mf * 2 + (e >> 1)] += ex2(acc[mf][nf][e]);
            } else {
                #pragma unroll
                for (int mf = 0; mf < 2; mf++)
                    #pragma unroll
                    for (int e = 0; e < 4; e++) {
                        const int ie = iw + mf * 16 + rquad + ((e & 2) ? 8 : 0);
                        const int je = jb + cpair + (e & 1);
                        const float d = acc[mf][nf][e];
                        if (je == ((ie + B_) & (N_ - 1))) g_pos[ie] = d;
                        rs[mf * 2 + (e >> 1)] += (je == ie) ? 0.f : ex2(d);
                    }
            }
        }

        if (t + 1 < TT) CP_WAIT0();
        __syncthreads();
    }

    // reduce rowsums across the lane quad
    #pragma unroll
    for (int r = 0; r < 4; r++) {
        rs[r] += __shfl_xor_sync(0xffffffffu, rs[r], 1);
        rs[r] += __shfl_xor_sync(0xffffffffu, rs[r], 2);
    }
    // 4 n-warps hold identical row sums? No: each covers different j cols ->
    // partial sums; accumulate atomically (16 adds per row total).
    if ((lane & 3) == 0) {
        #pragma unroll
        for (int r = 0; r < 4; r++) {
            const int row = iw + rquad + (r & 1) * 8 + (r >> 1) * 16;
            atomicAdd(&g_rowsum[row], rs[r]);
        }
    }
}

// ---------------------------------------------------------------- kernel 3
// loss_i = log(rowsum_i + 2^ps_i) - ps_i*ln2
__global__ void __launch_bounds__(1024) finalize_kernel(float* __restrict__ out)
{
    const int tid = threadIdx.x;
    float s = 0.f;
    #pragma unroll
    for (int r = tid; r < N_; r += 1024) {
        const float ps = g_pos[r];
        s += logf(g_rowsum[r] + ex2(ps)) - ps * LN2;
    }
    #pragma unroll
    for (int o = 16; o; o >>= 1) s += __shfl_xor_sync(0xffffffffu, s, o);
    __shared__ float sw[32];
    if ((tid & 31) == 0) sw[tid >> 5] = s;
    __syncthreads();
    if (tid < 32) {
        float v = sw[tid];
        #pragma unroll
        for (int o = 16; o; o >>= 1) v += __shfl_xor_sync(0xffffffffu, v, o);
        if (tid == 0) out[0] = v * (1.0f / (float)N_);
    }
}

// ---------------------------------------------------------------- launcher
extern "C" void kernel_launch(void* const* d_in, const int* in_sizes, int n_in,
                              void* d_out, int out_size)
{
    const float* zi = (const float*)d_in[0];
    const float* zj = (const float*)d_in[1];
    float* out = (float*)d_out;

    const int smem_bytes = 3 * MT * PITCH;   // A + 2x B buffers = 104448
    cudaFuncSetAttribute(ntxent_mma_kernel,
                         cudaFuncAttributeMaxDynamicSharedMemorySize, smem_bytes);

    normalize_kernel<<<N_ / 8, 256>>>(zi, zj);
    ntxent_mma_kernel<<<128, THREADS, smem_bytes>>>();
    finalize_kernel<<<1, 1024>>>(out);
}